// round 12
// baseline (speedup 1.0000x reference)
#include <cuda_runtime.h>
#include <cuda_fp16.h>
#include <cstdint>

// TriangleMultiplication, mma.sync m16n8k16 fp16, split-fp16 2-pass fp32 emu:
//   C = Ah*Bh + Al*Bh. R12: each CTA computes both N-halves sequentially
// (second A/H pass hits L2, halving DRAM read streams); gate stored fp16.

#define THREADS 256
#define OFF_A   0
#define OFF_B   16384
#define STAGE   24576
#define NSTAGE  3
#define OFF_MB  (STAGE*NSTAGE)        // full[0..2] +0,8,16 ; empty[0..2] +24,32,40
#define SMEM_TOTAL (STAGE*NSTAGE + 64)

#define NELEM 33554432            // 2*256*256*256
#define ACH 16777216UL            // A-family k-chunk stride (131072 rows * 128B)
#define BCH 16384UL               // B-family k-chunk stride (256 rows * 64B)
#define SLB 131072UL              // per-slice / per-weight B bytes (8 chunks)

// A-family images [kc8][m 131072][128B: hi 0-63 | lo 64-127], fp16
static __device__ __align__(16) __half g_P[2*NELEM];
static __device__ __align__(16) __half g_A[2*NELEM];
static __device__ __align__(16) __half g_H[2*NELEM];
// B-family images hi-only [.][kc8][row 256][64B], fp16
static __device__ __align__(16) __half g_B[NELEM];
static __device__ __align__(16) __half g_W[4*65536];
static __device__ __align__(16) __half g_G[NELEM];  // sigmoid gate fp16 natural [m][l]

__device__ __forceinline__ uint32_t pack_h2(__half x, __half y) {
    __half2 t = __halves2half2(x, y);
    return *reinterpret_cast<uint32_t*>(&t);
}
__device__ __forceinline__ uint32_t smem_u32(const void* p) {
    uint32_t a;
    asm("{ .reg .u64 t; cvta.to.shared.u64 t, %1; cvt.u32.u64 %0, t; }" : "=r"(a) : "l"(p));
    return a;
}
__device__ __forceinline__ void mma16816(float d[4], const uint32_t a[4], const uint32_t b[2]) {
    asm volatile(
        "mma.sync.aligned.m16n8k16.row.col.f32.f16.f16.f32 "
        "{%0,%1,%2,%3}, {%4,%5,%6,%7}, {%8,%9}, {%0,%1,%2,%3};"
        : "+f"(d[0]), "+f"(d[1]), "+f"(d[2]), "+f"(d[3])
        : "r"(a[0]), "r"(a[1]), "r"(a[2]), "r"(a[3]), "r"(b[0]), "r"(b[1]));
}
__device__ __forceinline__ void ldsm_x4(uint32_t r[4], uint32_t a) {
    asm volatile("ldmatrix.sync.aligned.m8n8.x4.shared.b16 {%0,%1,%2,%3}, [%4];"
        : "=r"(r[0]), "=r"(r[1]), "=r"(r[2]), "=r"(r[3]) : "r"(a));
}
__device__ __forceinline__ void split2(float x, float y, uint32_t& H, uint32_t& L) {
    __half hx = __float2half_rn(x), hy = __float2half_rn(y);
    __half lx = __float2half_rn(x - __half2float(hx));
    __half ly = __float2half_rn(y - __half2float(hy));
    H = pack_h2(hx, hy); L = pack_h2(lx, ly);
}

#define MBAR_INIT(a, n) asm volatile("mbarrier.init.shared.b64 [%0], %1;" :: "r"(a), "r"(n) : "memory")
#define MBAR_EXPECT(a, b) asm volatile("mbarrier.arrive.expect_tx.shared.b64 _, [%0], %1;" :: "r"(a), "r"(b) : "memory")
#define MBAR_ARRIVE(a) asm volatile("mbarrier.arrive.shared.b64 _, [%0];" :: "r"(a) : "memory")
#define MBAR_WAIT(a, ph) do { \
    uint32_t _m = (a), _p = (ph), _d; \
    asm volatile("{ .reg .pred p; mbarrier.try_wait.parity.acquire.cta.shared::cta.b64 p, [%1], %2; selp.b32 %0,1,0,p; }" \
        : "=r"(_d) : "r"(_m), "r"(_p) : "memory"); \
    if (!_d) { \
        asm volatile("{ .reg .pred P1; WL_%=: mbarrier.try_wait.parity.acquire.cta.shared::cta.b64 P1, [%0], %1, 0x989680; @P1 bra.uni WD_%=; bra.uni WL_%=; WD_%=: }" \
            :: "r"(_m), "r"(_p) : "memory"); \
    } } while (0)

__device__ __forceinline__ void bulk_cp(uint32_t dst, const char* src, uint32_t bytes, uint32_t mb) {
    asm volatile("cp.async.bulk.shared::cluster.global.mbarrier::complete_tx::bytes [%0], [%1], %2, [%3];"
        :: "r"(dst), "l"(src), "r"(bytes), "r"(mb) : "memory");
}

// A-family: 128B rows, chunk xor key r&7
__device__ __forceinline__ uint32_t inrowA(int r, int b) {
    return (uint32_t)(((((b >> 4) ^ (r & 7)) << 4)) | (b & 15));
}
__device__ __forceinline__ size_t off_hi(int row, int k) {
    return (size_t)(k >> 5) * ACH + (size_t)row * 128 + inrowA(row, (k & 31) * 2);
}
__device__ __forceinline__ size_t off_lo(int row, int k) {
    return (size_t)(k >> 5) * ACH + (size_t)row * 128 + inrowA(row, 64 + (k & 31) * 2);
}
// B-family: 64B rows, chunk xor key (r>>1)&3
__device__ __forceinline__ uint32_t inrowB(int r, int b) {
    return (uint32_t)(((((b >> 4) ^ ((r >> 1) & 3)) << 4)) | (b & 15));
}
__device__ __forceinline__ size_t off_b(int row, int k) {
    return (size_t)(k >> 5) * BCH + (size_t)row * 64 + inrowB(row, (k & 31) * 2);
}
__device__ __forceinline__ void store_splitA(char* base, int row, int k, float x, float y) {
    uint32_t H, L; split2(x, y, H, L);
    *(uint32_t*)(base + off_hi(row, k)) = H;
    *(uint32_t*)(base + off_lo(row, k)) = L;
}

__device__ __forceinline__ void issue_chunk(uint32_t sb, int st,
    const char* Aimg, const char* Bimg, int c)
{
    const uint32_t buf = sb + (uint32_t)st * STAGE;
    const uint32_t mb  = sb + OFF_MB + (uint32_t)st * 8;
    MBAR_EXPECT(mb, 24576u);
    bulk_cp(buf + OFF_A, Aimg + (size_t)c * ACH, 16384, mb);
    bulk_cp(buf + OFF_B, Bimg + (size_t)c * BCH, 8192, mb);
}

// acc[2][8][4]: warp tile 32x64 of C = A[128,256] @ B[128,256]^T-rows.
// Safe to call repeatedly (entry __syncthreads before barrier re-init).
__device__ __forceinline__ void gemm_compute(uint32_t sb,
    const char* __restrict__ Aimg, const char* __restrict__ Bimg,
    float acc[2][8][4])
{
    const int tid = threadIdx.x;
    const int lane = tid & 31, wid = tid >> 5;
    const int wm = wid >> 1, wn = wid & 1;

#pragma unroll
    for (int mt = 0; mt < 2; ++mt)
#pragma unroll
        for (int nt = 0; nt < 8; ++nt)
#pragma unroll
            for (int i = 0; i < 4; ++i) acc[mt][nt][i] = 0.f;

    __syncthreads();   // all warps past any previous use of barriers/smem
    if (tid == 0) {
#pragma unroll
        for (int s = 0; s < NSTAGE; ++s) {
            MBAR_INIT(sb + OFF_MB + s * 8, 1);       // full: tx-based
            MBAR_INIT(sb + OFF_MB + 24 + s * 8, 8);  // empty: 8 warp arrivals
        }
    }
    __syncthreads();
    if (tid == 0) {
        issue_chunk(sb, 0, Aimg, Bimg, 0);
        issue_chunk(sb, 1, Aimg, Bimg, 1);
    }

    const uint32_t xr     = lane & 7;
    const uint32_t a_base = (uint32_t)(wm*32 + (lane & 15)) * 128;
    const uint32_t a_kh   = lane >> 4;
    const uint32_t b_row  = (lane & 7) + ((lane & 16) >> 1);
    const uint32_t b_base = ((uint32_t)(wn*64) + b_row) * 64;
    const uint32_t b_kh   = (lane >> 3) & 1;
    const uint32_t bxr    = (lane & 6) >> 1;

#pragma unroll
    for (int c = 0; c < 8; ++c) {
        const int st = c % NSTAGE;
        if (tid == 0 && c + 2 < 8) {
            const int cn = c + 2, st2 = cn % NSTAGE;
            if (cn >= NSTAGE) { MBAR_WAIT(sb + OFF_MB + 24 + st2 * 8, ((cn - NSTAGE) / NSTAGE) & 1); }
            issue_chunk(sb, st2, Aimg, Bimg, cn);
        }
        MBAR_WAIT(sb + OFF_MB + st * 8, (c / NSTAGE) & 1);
        const uint32_t buf = sb + (uint32_t)st * STAGE;
#pragma unroll
        for (int s = 0; s < 2; ++s) {
            const uint32_t ach = (uint32_t)s*2 + a_kh;
            const uint32_t ax_h = ((ach ^ xr) << 4), ax_l = (((ach + 4) ^ xr) << 4);
            const uint32_t bx   = (((uint32_t)s*2 + b_kh) ^ bxr) << 4;
            uint32_t ah[2][4], al[2][4];
#pragma unroll
            for (int mt = 0; mt < 2; ++mt) {
                const uint32_t ao = buf + OFF_A + a_base + (uint32_t)mt*2048;
                ldsm_x4(ah[mt], ao + ax_h);
                ldsm_x4(al[mt], ao + ax_l);
            }
#pragma unroll
            for (int half = 0; half < 2; ++half) {
                uint32_t bh[2][4];
#pragma unroll
                for (int p = 0; p < 2; ++p) {
                    const uint32_t bo = buf + OFF_B + b_base + (uint32_t)(half*2 + p)*1024;
                    ldsm_x4(bh[p], bo + bx);
                }
#pragma unroll
                for (int mt = 0; mt < 2; ++mt)
#pragma unroll
                    for (int p = 0; p < 2; ++p)
#pragma unroll
                        for (int q = 0; q < 2; ++q)
                            mma16816(acc[mt][half*4 + p*2 + q], ah[mt], &bh[p][q*2]);
#pragma unroll
                for (int mt = 0; mt < 2; ++mt)
#pragma unroll
                    for (int p = 0; p < 2; ++p)
#pragma unroll
                        for (int q = 0; q < 2; ++q)
                            mma16816(acc[mt][half*4 + p*2 + q], al[mt], &bh[p][q*2]);
            }
        }
        if (lane == 0) MBAR_ARRIVE(sb + OFF_MB + 24 + st * 8);
    }
}

// ---------------- prep kernels ----------------

extern "C" __global__ void psplit_kernel(const float* __restrict__ pair)
{
    const size_t i = ((size_t)blockIdx.x * 256 + threadIdx.x) * 4;
    const int m = (int)(i >> 8), col = (int)(i & 255);
    float4 v = *(const float4*)(pair + i);
    uint32_t H0, L0, H1, L1;
    split2(v.x, v.y, H0, L0);
    split2(v.z, v.w, H1, L1);
    char* base = (char*)g_P;
    *(uint2*)(base + off_hi(m, col)) = make_uint2(H0, H1);
    *(uint2*)(base + off_lo(m, col)) = make_uint2(L0, L1);
}

extern "C" __global__ void wprep_kernel(const float* __restrict__ Wa,
                                        const float* __restrict__ Wb,
                                        const float* __restrict__ Wg,
                                        const float* __restrict__ Wo)
{
    const float* Ws[4] = {Wa, Wb, Wg, Wo};
    const int d = blockIdx.x, c = threadIdx.x;
    const size_t off = off_b(d, c);
#pragma unroll
    for (int w = 0; w < 4; ++w) {
        __half h = __float2half_rn(Ws[w][c*256 + d]);
        *(__half*)((char*)g_W + (size_t)w * SLB + off) = h;
    }
}

// ---------------- GEMM kernels ----------------

// grid (3, 1024): x = weight {a,b,g}, y = m-tile. Both N-halves per CTA.
extern "C" __global__ void __launch_bounds__(THREADS, 2)
proj_kernel(const float* __restrict__ ba, const float* __restrict__ bb,
            const float* __restrict__ bg)
{
    extern __shared__ char smem[];
    const uint32_t sb = smem_u32(smem);
    const int w = blockIdx.x;
    const int m0 = blockIdx.y * 128;

    const float* bias = (w == 0) ? ba : ((w == 1) ? bb : bg);
    const int wid = threadIdx.x >> 5, lane = threadIdx.x & 31;
    const int wm = wid >> 1, wn = wid & 1;
    const int g = lane >> 2, qc = lane & 3;

    for (int nt = 0; nt < 2; ++nt) {
        float acc[2][8][4];
        gemm_compute(sb,
                     (const char*)g_P + (size_t)m0*128,
                     (const char*)g_W + (size_t)w*SLB + (size_t)nt*8192,
                     acc);
        __syncthreads();   // ring stages idle before stg reuse

        if (w == 1) {
            float* stg = (float*)smem + wid * 2080;  // 32*65
#pragma unroll
            for (int mt = 0; mt < 2; ++mt)
#pragma unroll
                for (int ntl = 0; ntl < 8; ++ntl) {
                    const int rm = mt*16 + g, cn = ntl*8 + 2*qc;
                    float2 bv = *(const float2*)(bias + nt*128 + wn*64 + cn);
                    stg[rm*65 + cn]           = acc[mt][ntl][0] + bv.x;
                    stg[rm*65 + cn + 1]       = acc[mt][ntl][1] + bv.y;
                    stg[(rm + 8)*65 + cn]     = acc[mt][ntl][2] + bv.x;
                    stg[(rm + 8)*65 + cn + 1] = acc[mt][ntl][3] + bv.y;
                }
            __syncwarp();
            const int slice = m0 >> 8;
            const int j0 = (m0 & 255) + wm * 32;
            const int m2 = 2 * (lane & 15);
            const int j = j0 + m2;
            char* base = (char*)g_B + (size_t)slice * SLB;
            for (int r = lane >> 4; r < 64; r += 2) {
                const int l = nt*128 + wn*64 + r;
                uint32_t H = pack_h2(__float2half_rn(stg[m2*65 + r]),
                                     __float2half_rn(stg[(m2 + 1)*65 + r]));
                *(uint32_t*)(base + off_b(l, j)) = H;
            }
        } else {
#pragma unroll
            for (int mt = 0; mt < 2; ++mt) {
                const int R0 = m0 + wm*32 + mt*16 + g;
#pragma unroll
                for (int ntl = 0; ntl < 8; ++ntl) {
                    const int col = nt*128 + wn*64 + ntl*8 + 2*qc;
                    float2 bv = *(const float2*)(bias + col);
                    float v0 = acc[mt][ntl][0] + bv.x, v1 = acc[mt][ntl][1] + bv.y;
                    float v2 = acc[mt][ntl][2] + bv.x, v3 = acc[mt][ntl][3] + bv.y;
                    if (w == 2) {
                        v0 = 1.f/(1.f + __expf(-v0)); v1 = 1.f/(1.f + __expf(-v1));
                        v2 = 1.f/(1.f + __expf(-v2)); v3 = 1.f/(1.f + __expf(-v3));
                        *(uint32_t*)(g_G + (size_t)R0*256 + col) =
                            pack_h2(__float2half_rn(v0), __float2half_rn(v1));
                        *(uint32_t*)(g_G + (size_t)(R0 + 8)*256 + col) =
                            pack_h2(__float2half_rn(v2), __float2half_rn(v3));
                    } else {
                        store_splitA((char*)g_A, R0,     col, v0, v1);
                        store_splitA((char*)g_A, R0 + 8, col, v2, v3);
                    }
                }
            }
        }
    }
}

// grid (2, 512): x = jt, y = slice. Both lt-halves per CTA. h = g*(a_s@b_s).
extern "C" __global__ void __launch_bounds__(THREADS, 2)
tri_kernel()
{
    extern __shared__ char smem[];
    const uint32_t sb = smem_u32(smem);
    const int jt = blockIdx.x, slice = blockIdx.y;

    const int wid = threadIdx.x >> 5, lane = threadIdx.x & 31;
    const int wm = wid >> 1, wn = wid & 1;
    const int g = lane >> 2, qc = lane & 3;
    const int mbase = slice*256 + jt*128 + wm*32;

    for (int lt = 0; lt < 2; ++lt) {
        float acc[2][8][4];
        gemm_compute(sb,
                     (const char*)g_A + (size_t)(slice*256 + jt*128)*128,
                     (const char*)g_B + (size_t)slice*SLB + (size_t)lt*8192,
                     acc);

#pragma unroll
        for (int mt = 0; mt < 2; ++mt) {
            const int R0 = mbase + mt*16 + g;
#pragma unroll
            for (int ntl = 0; ntl < 8; ++ntl) {
                const int col = lt*128 + wn*64 + ntl*8 + 2*qc;
                __half2 h0 = *(const __half2*)(g_G + (size_t)R0*256 + col);
                __half2 h1 = *(const __half2*)(g_G + (size_t)(R0 + 8)*256 + col);
                float2 g0 = __half22float2(h0);
                float2 g1 = __half22float2(h1);
                store_splitA((char*)g_H, R0,     col, acc[mt][ntl][0]*g0.x, acc[mt][ntl][1]*g0.y);
                store_splitA((char*)g_H, R0 + 8, col, acc[mt][ntl][2]*g1.x, acc[mt][ntl][3]*g1.y);
            }
        }
    }
}

// grid 1024: m-tile. Both nt-halves per CTA. out = H @ Wo^T-rows + bo.
extern "C" __global__ void __launch_bounds__(THREADS, 2)
out_kernel(const float* __restrict__ bo, float* __restrict__ out)
{
    extern __shared__ char smem[];
    const uint32_t sb = smem_u32(smem);
    const int m0 = blockIdx.x * 128;

    const int wid = threadIdx.x >> 5, lane = threadIdx.x & 31;
    const int wm = wid >> 1, wn = wid & 1;
    const int g = lane >> 2, qc = lane & 3;

    for (int nt = 0; nt < 2; ++nt) {
        float acc[2][8][4];
        gemm_compute(sb,
                     (const char*)g_H + (size_t)m0*128,
                     (const char*)g_W + (size_t)3*SLB + (size_t)nt*8192,
                     acc);

#pragma unroll
        for (int mt = 0; mt < 2; ++mt) {
            const int R0 = m0 + wm*32 + mt*16 + g;
#pragma unroll
            for (int ntl = 0; ntl < 8; ++ntl) {
                const int col = nt*128 + wn*64 + ntl*8 + 2*qc;
                float2 bv = *(const float2*)(bo + col);
                *(float2*)(out + (size_t)R0*256 + col) =
                    make_float2(acc[mt][ntl][0] + bv.x, acc[mt][ntl][1] + bv.y);
                *(float2*)(out + (size_t)(R0 + 8)*256 + col) =
                    make_float2(acc[mt][ntl][2] + bv.x, acc[mt][ntl][3] + bv.y);
            }
        }
    }
}

extern "C" void kernel_launch(void* const* d_in, const int* in_sizes, int n_in,
                              void* d_out, int out_size)
{
    const float* pair = (const float*)d_in[0];
    const float* Wa   = (const float*)d_in[1];
    const float* ba   = (const float*)d_in[2];
    const float* Wb   = (const float*)d_in[3];
    const float* bb   = (const float*)d_in[4];
    const float* Wg   = (const float*)d_in[5];
    const float* bg   = (const float*)d_in[6];
    const float* Wo   = (const float*)d_in[7];
    const float* bo   = (const float*)d_in[8];
    float* out = (float*)d_out;

    cudaFuncSetAttribute(proj_kernel, cudaFuncAttributeMaxDynamicSharedMemorySize, SMEM_TOTAL);
    cudaFuncSetAttribute(tri_kernel,  cudaFuncAttributeMaxDynamicSharedMemorySize, SMEM_TOTAL);
    cudaFuncSetAttribute(out_kernel,  cudaFuncAttributeMaxDynamicSharedMemorySize, SMEM_TOTAL);

    wprep_kernel <<<256,   256>>>(Wa, Wb, Wg, Wo);
    psplit_kernel<<<32768, 256>>>(pair);
    proj_kernel<<<dim3(3, 1024), THREADS, SMEM_TOTAL>>>(ba, bb, bg);
    tri_kernel <<<dim3(2, 512),  THREADS, SMEM_TOTAL>>>();
    out_kernel <<<1024,          THREADS, SMEM_TOTAL>>>(bo, out);
}

// round 14
// speedup vs baseline: 1.1910x; 1.1910x over previous
#include <cuda_runtime.h>
#include <cuda_fp16.h>
#include <cstdint>

// TriangleMultiplication, mma.sync m16n8k16 fp16, split-fp16 fp32 emu.
// R14 = R11 + proj made SINGLE-pass by storing pair fp16 hi-only (earliest-
// stage rounding; R13 showed final-stage rounding is ~10x costlier, so H
// stays split and out stays 2-pass; gate stays fp32).

#define THREADS 256
// wide pipeline (tri/out): A 16KB split + B 8KB
#define OFF_A   0
#define OFF_B   16384
#define STAGE   24576
// narrow pipeline (proj): A 8KB hi-only + B 8KB
#define OFF_B1  8192
#define STAGE1  16384
#define NSTAGE  3
#define OFF_MB  73728                 // full[0..2] +0,8,16 ; empty[0..2] +24,32,40
#define SMEM_TOTAL 73792

#define NELEM 33554432            // 2*256*256*256
#define ACH 16777216UL            // wide A k-chunk stride (131072 rows * 128B)
#define HCH 8388608UL             // narrow k-chunk stride (131072 rows * 64B)
#define BCH 16384UL               // B-family k-chunk stride (256 rows * 64B)
#define SLB 131072UL              // per-slice / per-weight B bytes (8 chunks)

// narrow hi-only pair image [kc8][m][64B]
static __device__ __align__(16) __half g_P[NELEM];
// wide split images [kc8][m][128B: hi|lo]
static __device__ __align__(16) __half g_A[2*NELEM];
static __device__ __align__(16) __half g_H[2*NELEM];
// B-family hi-only images [.][kc8][row 256][64B]
static __device__ __align__(16) __half g_B[NELEM];
static __device__ __align__(16) __half g_W[4*65536];
static __device__ float g_G[NELEM];   // sigmoid gate fp32 natural [m][l]

__device__ __forceinline__ uint32_t pack_h2(__half x, __half y) {
    __half2 t = __halves2half2(x, y);
    return *reinterpret_cast<uint32_t*>(&t);
}
__device__ __forceinline__ uint32_t smem_u32(const void* p) {
    uint32_t a;
    asm("{ .reg .u64 t; cvta.to.shared.u64 t, %1; cvt.u32.u64 %0, t; }" : "=r"(a) : "l"(p));
    return a;
}
__device__ __forceinline__ void mma16816(float d[4], const uint32_t a[4], const uint32_t b[2]) {
    asm volatile(
        "mma.sync.aligned.m16n8k16.row.col.f32.f16.f16.f32 "
        "{%0,%1,%2,%3}, {%4,%5,%6,%7}, {%8,%9}, {%0,%1,%2,%3};"
        : "+f"(d[0]), "+f"(d[1]), "+f"(d[2]), "+f"(d[3])
        : "r"(a[0]), "r"(a[1]), "r"(a[2]), "r"(a[3]), "r"(b[0]), "r"(b[1]));
}
__device__ __forceinline__ void ldsm_x4(uint32_t r[4], uint32_t a) {
    asm volatile("ldmatrix.sync.aligned.m8n8.x4.shared.b16 {%0,%1,%2,%3}, [%4];"
        : "=r"(r[0]), "=r"(r[1]), "=r"(r[2]), "=r"(r[3]) : "r"(a));
}
__device__ __forceinline__ void split2(float x, float y, uint32_t& H, uint32_t& L) {
    __half hx = __float2half_rn(x), hy = __float2half_rn(y);
    __half lx = __float2half_rn(x - __half2float(hx));
    __half ly = __float2half_rn(y - __half2float(hy));
    H = pack_h2(hx, hy); L = pack_h2(lx, ly);
}

#define MBAR_INIT(a, n) asm volatile("mbarrier.init.shared.b64 [%0], %1;" :: "r"(a), "r"(n) : "memory")
#define MBAR_EXPECT(a, b) asm volatile("mbarrier.arrive.expect_tx.shared.b64 _, [%0], %1;" :: "r"(a), "r"(b) : "memory")
#define MBAR_ARRIVE(a) asm volatile("mbarrier.arrive.shared.b64 _, [%0];" :: "r"(a) : "memory")
#define MBAR_WAIT(a, ph) do { \
    uint32_t _m = (a), _p = (ph), _d; \
    asm volatile("{ .reg .pred p; mbarrier.try_wait.parity.acquire.cta.shared::cta.b64 p, [%1], %2; selp.b32 %0,1,0,p; }" \
        : "=r"(_d) : "r"(_m), "r"(_p) : "memory"); \
    if (!_d) { \
        asm volatile("{ .reg .pred P1; WL_%=: mbarrier.try_wait.parity.acquire.cta.shared::cta.b64 P1, [%0], %1, 0x989680; @P1 bra.uni WD_%=; bra.uni WL_%=; WD_%=: }" \
            :: "r"(_m), "r"(_p) : "memory"); \
    } } while (0)

__device__ __forceinline__ void bulk_cp(uint32_t dst, const char* src, uint32_t bytes, uint32_t mb) {
    asm volatile("cp.async.bulk.shared::cluster.global.mbarrier::complete_tx::bytes [%0], [%1], %2, [%3];"
        :: "r"(dst), "l"(src), "r"(bytes), "r"(mb) : "memory");
}

// wide rows (128B): chunk xor key r&7
__device__ __forceinline__ uint32_t inrowA(int r, int b) {
    return (uint32_t)(((((b >> 4) ^ (r & 7)) << 4)) | (b & 15));
}
__device__ __forceinline__ size_t off_hi(int row, int k) {
    return (size_t)(k >> 5) * ACH + (size_t)row * 128 + inrowA(row, (k & 31) * 2);
}
__device__ __forceinline__ size_t off_lo(int row, int k) {
    return (size_t)(k >> 5) * ACH + (size_t)row * 128 + inrowA(row, 64 + (k & 31) * 2);
}
// narrow rows (64B): chunk xor key (r>>1)&3
__device__ __forceinline__ uint32_t inrowB(int r, int b) {
    return (uint32_t)(((((b >> 4) ^ ((r >> 1) & 3)) << 4)) | (b & 15));
}
__device__ __forceinline__ size_t off_b(int row, int k) {       // B-family (256-row chunks)
    return (size_t)(k >> 5) * BCH + (size_t)row * 64 + inrowB(row, (k & 31) * 2);
}
__device__ __forceinline__ size_t off_n(int row, int k) {       // narrow P (131072-row chunks)
    return (size_t)(k >> 5) * HCH + (size_t)row * 64 + inrowB(row, (k & 31) * 2);
}
__device__ __forceinline__ void store_splitA(char* base, int row, int k, float x, float y) {
    uint32_t H, L; split2(x, y, H, L);
    *(uint32_t*)(base + off_hi(row, k)) = H;
    *(uint32_t*)(base + off_lo(row, k)) = L;
}

// ---------------- wide GEMM (tri/out): A split hi/lo, 2-pass ----------------

__device__ __forceinline__ void issue_chunk(uint32_t sb, int st,
    const char* Aimg, const char* Bimg, int c)
{
    const uint32_t buf = sb + (uint32_t)st * STAGE;
    const uint32_t mb  = sb + OFF_MB + (uint32_t)st * 8;
    MBAR_EXPECT(mb, 24576u);
    bulk_cp(buf + OFF_A, Aimg + (size_t)c * ACH, 16384, mb);
    bulk_cp(buf + OFF_B, Bimg + (size_t)c * BCH, 8192, mb);
}

__device__ __forceinline__ void gemm_compute(uint32_t sb,
    const char* __restrict__ Aimg, const char* __restrict__ Bimg,
    float acc[2][8][4])
{
    const int tid = threadIdx.x;
    const int lane = tid & 31, wid = tid >> 5;
    const int wm = wid >> 1, wn = wid & 1;

#pragma unroll
    for (int mt = 0; mt < 2; ++mt)
#pragma unroll
        for (int nt = 0; nt < 8; ++nt)
#pragma unroll
            for (int i = 0; i < 4; ++i) acc[mt][nt][i] = 0.f;

    if (tid == 0) {
#pragma unroll
        for (int s = 0; s < NSTAGE; ++s) {
            MBAR_INIT(sb + OFF_MB + s * 8, 1);
            MBAR_INIT(sb + OFF_MB + 24 + s * 8, 8);
        }
    }
    __syncthreads();
    if (tid == 0) {
        issue_chunk(sb, 0, Aimg, Bimg, 0);
        issue_chunk(sb, 1, Aimg, Bimg, 1);
    }

    const uint32_t xr     = lane & 7;
    const uint32_t a_base = (uint32_t)(wm*32 + (lane & 15)) * 128;
    const uint32_t a_kh   = lane >> 4;
    const uint32_t b_row  = (lane & 7) + ((lane & 16) >> 1);
    const uint32_t b_base = ((uint32_t)(wn*64) + b_row) * 64;
    const uint32_t b_kh   = (lane >> 3) & 1;
    const uint32_t bxr    = (lane & 6) >> 1;

#pragma unroll
    for (int c = 0; c < 8; ++c) {
        const int st = c % NSTAGE;
        if (tid == 0 && c + 2 < 8) {
            const int cn = c + 2, st2 = cn % NSTAGE;
            if (cn >= NSTAGE) { MBAR_WAIT(sb + OFF_MB + 24 + st2 * 8, ((cn - NSTAGE) / NSTAGE) & 1); }
            issue_chunk(sb, st2, Aimg, Bimg, cn);
        }
        MBAR_WAIT(sb + OFF_MB + st * 8, (c / NSTAGE) & 1);
        const uint32_t buf = sb + (uint32_t)st * STAGE;
#pragma unroll
        for (int s = 0; s < 2; ++s) {
            const uint32_t ach = (uint32_t)s*2 + a_kh;
            const uint32_t ax_h = ((ach ^ xr) << 4), ax_l = (((ach + 4) ^ xr) << 4);
            const uint32_t bx   = (((uint32_t)s*2 + b_kh) ^ bxr) << 4;
            uint32_t ah[2][4], al[2][4];
#pragma unroll
            for (int mt = 0; mt < 2; ++mt) {
                const uint32_t ao = buf + OFF_A + a_base + (uint32_t)mt*2048;
                ldsm_x4(ah[mt], ao + ax_h);
                ldsm_x4(al[mt], ao + ax_l);
            }
#pragma unroll
            for (int half = 0; half < 2; ++half) {
                uint32_t bh[2][4];
#pragma unroll
                for (int p = 0; p < 2; ++p) {
                    const uint32_t bo = buf + OFF_B + b_base + (uint32_t)(half*2 + p)*1024;
                    ldsm_x4(bh[p], bo + bx);
                }
#pragma unroll
                for (int mt = 0; mt < 2; ++mt)
#pragma unroll
                    for (int p = 0; p < 2; ++p)
#pragma unroll
                        for (int q = 0; q < 2; ++q)
                            mma16816(acc[mt][half*4 + p*2 + q], ah[mt], &bh[p][q*2]);
#pragma unroll
                for (int mt = 0; mt < 2; ++mt)
#pragma unroll
                    for (int p = 0; p < 2; ++p)
#pragma unroll
                        for (int q = 0; q < 2; ++q)
                            mma16816(acc[mt][half*4 + p*2 + q], al[mt], &bh[p][q*2]);
            }
        }
        if (lane == 0) MBAR_ARRIVE(sb + OFF_MB + 24 + st * 8);
    }
}

// ---------------- narrow GEMM (proj): A hi-only, single pass ----------------

__device__ __forceinline__ void issue_chunk1(uint32_t sb, int st,
    const char* Aimg, const char* Bimg, int c)
{
    const uint32_t buf = sb + (uint32_t)st * STAGE1;
    const uint32_t mb  = sb + OFF_MB + (uint32_t)st * 8;
    MBAR_EXPECT(mb, 16384u);
    bulk_cp(buf,          Aimg + (size_t)c * HCH, 8192, mb);
    bulk_cp(buf + OFF_B1, Bimg + (size_t)c * BCH, 8192, mb);
}

__device__ __forceinline__ void gemm_compute1(uint32_t sb,
    const char* __restrict__ Aimg, const char* __restrict__ Bimg,
    float acc[2][8][4])
{
    const int tid = threadIdx.x;
    const int lane = tid & 31, wid = tid >> 5;
    const int wm = wid >> 1, wn = wid & 1;

#pragma unroll
    for (int mt = 0; mt < 2; ++mt)
#pragma unroll
        for (int nt = 0; nt < 8; ++nt)
#pragma unroll
            for (int i = 0; i < 4; ++i) acc[mt][nt][i] = 0.f;

    if (tid == 0) {
#pragma unroll
        for (int s = 0; s < NSTAGE; ++s) {
            MBAR_INIT(sb + OFF_MB + s * 8, 1);
            MBAR_INIT(sb + OFF_MB + 24 + s * 8, 8);
        }
    }
    __syncthreads();
    if (tid == 0) {
        issue_chunk1(sb, 0, Aimg, Bimg, 0);
        issue_chunk1(sb, 1, Aimg, Bimg, 1);
    }

    const uint32_t a_base = (uint32_t)(wm*32 + (lane & 15)) * 64;
    const uint32_t a_kh   = lane >> 4;
    const uint32_t axr    = (lane >> 1) & 3;
    const uint32_t b_row  = (lane & 7) + ((lane & 16) >> 1);
    const uint32_t b_base = ((uint32_t)(wn*64) + b_row) * 64;
    const uint32_t b_kh   = (lane >> 3) & 1;
    const uint32_t bxr    = (lane & 6) >> 1;

#pragma unroll
    for (int c = 0; c < 8; ++c) {
        const int st = c % NSTAGE;
        if (tid == 0 && c + 2 < 8) {
            const int cn = c + 2, st2 = cn % NSTAGE;
            if (cn >= NSTAGE) { MBAR_WAIT(sb + OFF_MB + 24 + st2 * 8, ((cn - NSTAGE) / NSTAGE) & 1); }
            issue_chunk1(sb, st2, Aimg, Bimg, cn);
        }
        MBAR_WAIT(sb + OFF_MB + st * 8, (c / NSTAGE) & 1);
        const uint32_t buf = sb + (uint32_t)st * STAGE1;
#pragma unroll
        for (int s = 0; s < 2; ++s) {
            const uint32_t ax = (((uint32_t)s*2 + a_kh) ^ axr) << 4;
            const uint32_t bx = (((uint32_t)s*2 + b_kh) ^ bxr) << 4;
            uint32_t ah[2][4];
#pragma unroll
            for (int mt = 0; mt < 2; ++mt)
                ldsm_x4(ah[mt], buf + a_base + (uint32_t)mt*1024 + ax);
#pragma unroll
            for (int half = 0; half < 2; ++half) {
                uint32_t bh[2][4];
#pragma unroll
                for (int p = 0; p < 2; ++p) {
                    const uint32_t bo = buf + OFF_B1 + b_base + (uint32_t)(half*2 + p)*1024;
                    ldsm_x4(bh[p], bo + bx);
                }
#pragma unroll
                for (int mt = 0; mt < 2; ++mt)
#pragma unroll
                    for (int p = 0; p < 2; ++p)
#pragma unroll
                        for (int q = 0; q < 2; ++q)
                            mma16816(acc[mt][half*4 + p*2 + q], ah[mt], &bh[p][q*2]);
            }
        }
        if (lane == 0) MBAR_ARRIVE(sb + OFF_MB + 24 + st * 8);
    }
}

// ---------------- prep kernels ----------------

// pair fp32 -> narrow fp16 hi-only image
extern "C" __global__ void psplit_kernel(const float* __restrict__ pair)
{
    const size_t i = ((size_t)blockIdx.x * 256 + threadIdx.x) * 4;
    const int m = (int)(i >> 8), col = (int)(i & 255);
    float4 v = *(const float4*)(pair + i);
    uint32_t h01 = pack_h2(__float2half_rn(v.x), __float2half_rn(v.y));
    uint32_t h23 = pack_h2(__float2half_rn(v.z), __float2half_rn(v.w));
    *(uint2*)((char*)g_P + off_n(m, col)) = make_uint2(h01, h23);
}

extern "C" __global__ void wprep_kernel(const float* __restrict__ Wa,
                                        const float* __restrict__ Wb,
                                        const float* __restrict__ Wg,
                                        const float* __restrict__ Wo)
{
    const float* Ws[4] = {Wa, Wb, Wg, Wo};
    const int d = blockIdx.x, c = threadIdx.x;
    const size_t off = off_b(d, c);
#pragma unroll
    for (int w = 0; w < 4; ++w) {
        __half h = __float2half_rn(Ws[w][c*256 + d]);
        *(__half*)((char*)g_W + (size_t)w * SLB + off) = h;
    }
}

// ---------------- GEMM kernels ----------------

// grid (6, 1024): x = w*2 + nt, y = m-tile. Single-pass narrow GEMM.
extern "C" __global__ void __launch_bounds__(THREADS, 2)
proj_kernel(const float* __restrict__ ba, const float* __restrict__ bb,
            const float* __restrict__ bg)
{
    extern __shared__ char smem[];
    const uint32_t sb = smem_u32(smem);
    const int w = blockIdx.x >> 1, nt = blockIdx.x & 1;
    const int m0 = blockIdx.y * 128;

    float acc[2][8][4];
    gemm_compute1(sb,
                  (const char*)g_P + (size_t)m0*64,
                  (const char*)g_W + (size_t)w*SLB + (size_t)nt*8192,
                  acc);
    __syncthreads();

    const float* bias = (w == 0) ? ba : ((w == 1) ? bb : bg);
    const int wid = threadIdx.x >> 5, lane = threadIdx.x & 31;
    const int wm = wid >> 1, wn = wid & 1;
    const int g = lane >> 2, qc = lane & 3;

    if (w == 1) {
        // stage warp tile [32 m][64 n] fp32 -> transposed hi-only store to g_B
        float* stg = (float*)smem + wid * 2080;  // 32*65
#pragma unroll
        for (int mt = 0; mt < 2; ++mt)
#pragma unroll
            for (int ntl = 0; ntl < 8; ++ntl) {
                const int rm = mt*16 + g, cn = ntl*8 + 2*qc;
                float2 bv = *(const float2*)(bias + nt*128 + wn*64 + cn);
                stg[rm*65 + cn]           = acc[mt][ntl][0] + bv.x;
                stg[rm*65 + cn + 1]       = acc[mt][ntl][1] + bv.y;
                stg[(rm + 8)*65 + cn]     = acc[mt][ntl][2] + bv.x;
                stg[(rm + 8)*65 + cn + 1] = acc[mt][ntl][3] + bv.y;
            }
        __syncwarp();
        const int slice = m0 >> 8;
        const int j0 = (m0 & 255) + wm * 32;
        const int m2 = 2 * (lane & 15);
        const int j = j0 + m2;
        char* base = (char*)g_B + (size_t)slice * SLB;
        for (int r = lane >> 4; r < 64; r += 2) {
            const int l = nt*128 + wn*64 + r;
            uint32_t H = pack_h2(__float2half_rn(stg[m2*65 + r]),
                                 __float2half_rn(stg[(m2 + 1)*65 + r]));
            *(uint32_t*)(base + off_b(l, j)) = H;
        }
    } else {
#pragma unroll
        for (int mt = 0; mt < 2; ++mt) {
            const int R0 = m0 + wm*32 + mt*16 + g;
#pragma unroll
            for (int ntl = 0; ntl < 8; ++ntl) {
                const int col = nt*128 + wn*64 + ntl*8 + 2*qc;
                float2 bv = *(const float2*)(bias + col);
                float v0 = acc[mt][ntl][0] + bv.x, v1 = acc[mt][ntl][1] + bv.y;
                float v2 = acc[mt][ntl][2] + bv.x, v3 = acc[mt][ntl][3] + bv.y;
                if (w == 2) {
                    v0 = 1.f/(1.f + __expf(-v0)); v1 = 1.f/(1.f + __expf(-v1));
                    v2 = 1.f/(1.f + __expf(-v2)); v3 = 1.f/(1.f + __expf(-v3));
                    *(float2*)(g_G + (size_t)R0*256 + col)       = make_float2(v0, v1);
                    *(float2*)(g_G + (size_t)(R0 + 8)*256 + col) = make_float2(v2, v3);
                } else {
                    store_splitA((char*)g_A, R0,     col, v0, v1);
                    store_splitA((char*)g_A, R0 + 8, col, v2, v3);
                }
            }
        }
    }
}

// grid (4, 512): x = jt + 2*lt, y = slice. h = g * (a_s @ b_s), split store.
extern "C" __global__ void __launch_bounds__(THREADS, 2)
tri_kernel()
{
    extern __shared__ char smem[];
    const uint32_t sb = smem_u32(smem);
    const int jt = blockIdx.x & 1, lt = blockIdx.x >> 1;
    const int slice = blockIdx.y;

    float acc[2][8][4];
    gemm_compute(sb,
                 (const char*)g_A + (size_t)(slice*256 + jt*128)*128,
                 (const char*)g_B + (size_t)slice*SLB + (size_t)lt*8192,
                 acc);

    const int wid = threadIdx.x >> 5, lane = threadIdx.x & 31;
    const int wm = wid >> 1, wn = wid & 1;
    const int g = lane >> 2, qc = lane & 3;
    const int mbase = slice*256 + jt*128 + wm*32;

#pragma unroll
    for (int mt = 0; mt < 2; ++mt) {
        const int R0 = mbase + mt*16 + g;
#pragma unroll
        for (int ntl = 0; ntl < 8; ++ntl) {
            const int col = lt*128 + wn*64 + ntl*8 + 2*qc;
            float2 g0 = *(const float2*)(g_G + (size_t)R0*256 + col);
            float2 g1 = *(const float2*)(g_G + (size_t)(R0 + 8)*256 + col);
            store_splitA((char*)g_H, R0,     col, acc[mt][ntl][0]*g0.x, acc[mt][ntl][1]*g0.y);
            store_splitA((char*)g_H, R0 + 8, col, acc[mt][ntl][2]*g1.x, acc[mt][ntl][3]*g1.y);
        }
    }
}

// grid (2, 1024): x = nt, y = m-tile. out = H @ Wo^T-rows + bo (2-pass, exact H).
extern "C" __global__ void __launch_bounds__(THREADS, 2)
out_kernel(const float* __restrict__ bo, float* __restrict__ out)
{
    extern __shared__ char smem[];
    const uint32_t sb = smem_u32(smem);
    const int nt = blockIdx.x;
    const int m0 = blockIdx.y * 128;

    float acc[2][8][4];
    gemm_compute(sb,
                 (const char*)g_H + (size_t)m0*128,
                 (const char*)g_W + (size_t)3*SLB + (size_t)nt*8192,
                 acc);

    const int wid = threadIdx.x >> 5, lane = threadIdx.x & 31;
    const int wm = wid >> 1, wn = wid & 1;
    const int g = lane >> 2, qc = lane & 3;

#pragma unroll
    for (int mt = 0; mt < 2; ++mt) {
        const int R0 = m0 + wm*32 + mt*16 + g;
#pragma unroll
        for (int ntl = 0; ntl < 8; ++ntl) {
            const int col = nt*128 + wn*64 + ntl*8 + 2*qc;
            float2 bv = *(const float2*)(bo + col);
            *(float2*)(out + (size_t)R0*256 + col) =
                make_float2(acc[mt][ntl][0] + bv.x, acc[mt][ntl][1] + bv.y);
            *(float2*)(out + (size_t)(R0 + 8)*256 + col) =
                make_float2(acc[mt][ntl][2] + bv.x, acc[mt][ntl][3] + bv.y);
        }
    }
}

extern "C" void kernel_launch(void* const* d_in, const int* in_sizes, int n_in,
                              void* d_out, int out_size)
{
    const float* pair = (const float*)d_in[0];
    const float* Wa   = (const float*)d_in[1];
    const float* ba   = (const float*)d_in[2];
    const float* Wb   = (const float*)d_in[3];
    const float* bb   = (const float*)d_in[4];
    const float* Wg   = (const float*)d_in[5];
    const float* bg   = (const float*)d_in[6];
    const float* Wo   = (const float*)d_in[7];
    const float* bo   = (const float*)d_in[8];
    float* out = (float*)d_out;

    cudaFuncSetAttribute(proj_kernel, cudaFuncAttributeMaxDynamicSharedMemorySize, SMEM_TOTAL);
    cudaFuncSetAttribute(tri_kernel,  cudaFuncAttributeMaxDynamicSharedMemorySize, SMEM_TOTAL);
    cudaFuncSetAttribute(out_kernel,  cudaFuncAttributeMaxDynamicSharedMemorySize, SMEM_TOTAL);

    wprep_kernel <<<256,   256>>>(Wa, Wb, Wg, Wo);
    psplit_kernel<<<32768, 256>>>(pair);
    proj_kernel<<<dim3(6, 1024), THREADS, SMEM_TOTAL>>>(ba, bb, bg);
    tri_kernel <<<dim3(4, 512),  THREADS, SMEM_TOTAL>>>();
    out_kernel <<<dim3(2, 1024), THREADS, SMEM_TOTAL>>>(bo, out);
}

// round 15
// speedup vs baseline: 1.2538x; 1.0527x over previous
#include <cuda_runtime.h>
#include <cuda_fp16.h>
#include <cstdint>

// TriangleMultiplication, mma.sync m16n8k16 fp16, split-fp16 fp32 emu.
// R15 = R14 + a-projection stored fp16 hi-only (symmetric to b, which has
// been hi-only since R11 with ~2e-4 contribution) => tri is SINGLE-pass.
// H stays split / out stays 2-pass (R13: final-stage rounding is ~10x worse).

#define THREADS 256
// wide pipeline (out): A 16KB split + B 8KB
#define OFF_A   0
#define OFF_B   16384
#define STAGE   24576
// narrow pipeline (proj/tri): A 8KB hi-only + B 8KB
#define OFF_B1  8192
#define STAGE1  16384
#define NSTAGE  3
#define OFF_MB  73728                 // full[0..2] +0,8,16 ; empty[0..2] +24,32,40
#define SMEM_TOTAL 73792

#define NELEM 33554432            // 2*256*256*256
#define ACH 16777216UL            // wide A k-chunk stride (131072 rows * 128B)
#define HCH 8388608UL             // narrow k-chunk stride (131072 rows * 64B)
#define BCH 16384UL               // B-family k-chunk stride (256 rows * 64B)
#define SLB 131072UL              // per-slice / per-weight B bytes (8 chunks)

// narrow hi-only images [kc8][m][64B]
static __device__ __align__(16) __half g_P[NELEM];
static __device__ __align__(16) __half g_A[NELEM];
// wide split image [kc8][m][128B: hi|lo]
static __device__ __align__(16) __half g_H[2*NELEM];
// B-family hi-only images [.][kc8][row 256][64B]
static __device__ __align__(16) __half g_B[NELEM];
static __device__ __align__(16) __half g_W[4*65536];
static __device__ float g_G[NELEM];   // sigmoid gate fp32 natural [m][l]

__device__ __forceinline__ uint32_t pack_h2(__half x, __half y) {
    __half2 t = __halves2half2(x, y);
    return *reinterpret_cast<uint32_t*>(&t);
}
__device__ __forceinline__ uint32_t smem_u32(const void* p) {
    uint32_t a;
    asm("{ .reg .u64 t; cvta.to.shared.u64 t, %1; cvt.u32.u64 %0, t; }" : "=r"(a) : "l"(p));
    return a;
}
__device__ __forceinline__ void mma16816(float d[4], const uint32_t a[4], const uint32_t b[2]) {
    asm volatile(
        "mma.sync.aligned.m16n8k16.row.col.f32.f16.f16.f32 "
        "{%0,%1,%2,%3}, {%4,%5,%6,%7}, {%8,%9}, {%0,%1,%2,%3};"
        : "+f"(d[0]), "+f"(d[1]), "+f"(d[2]), "+f"(d[3])
        : "r"(a[0]), "r"(a[1]), "r"(a[2]), "r"(a[3]), "r"(b[0]), "r"(b[1]));
}
__device__ __forceinline__ void ldsm_x4(uint32_t r[4], uint32_t a) {
    asm volatile("ldmatrix.sync.aligned.m8n8.x4.shared.b16 {%0,%1,%2,%3}, [%4];"
        : "=r"(r[0]), "=r"(r[1]), "=r"(r[2]), "=r"(r[3]) : "r"(a));
}
__device__ __forceinline__ void split2(float x, float y, uint32_t& H, uint32_t& L) {
    __half hx = __float2half_rn(x), hy = __float2half_rn(y);
    __half lx = __float2half_rn(x - __half2float(hx));
    __half ly = __float2half_rn(y - __half2float(hy));
    H = pack_h2(hx, hy); L = pack_h2(lx, ly);
}

#define MBAR_INIT(a, n) asm volatile("mbarrier.init.shared.b64 [%0], %1;" :: "r"(a), "r"(n) : "memory")
#define MBAR_EXPECT(a, b) asm volatile("mbarrier.arrive.expect_tx.shared.b64 _, [%0], %1;" :: "r"(a), "r"(b) : "memory")
#define MBAR_ARRIVE(a) asm volatile("mbarrier.arrive.shared.b64 _, [%0];" :: "r"(a) : "memory")
#define MBAR_WAIT(a, ph) do { \
    uint32_t _m = (a), _p = (ph), _d; \
    asm volatile("{ .reg .pred p; mbarrier.try_wait.parity.acquire.cta.shared::cta.b64 p, [%1], %2; selp.b32 %0,1,0,p; }" \
        : "=r"(_d) : "r"(_m), "r"(_p) : "memory"); \
    if (!_d) { \
        asm volatile("{ .reg .pred P1; WL_%=: mbarrier.try_wait.parity.acquire.cta.shared::cta.b64 P1, [%0], %1, 0x989680; @P1 bra.uni WD_%=; bra.uni WL_%=; WD_%=: }" \
            :: "r"(_m), "r"(_p) : "memory"); \
    } } while (0)

__device__ __forceinline__ void bulk_cp(uint32_t dst, const char* src, uint32_t bytes, uint32_t mb) {
    asm volatile("cp.async.bulk.shared::cluster.global.mbarrier::complete_tx::bytes [%0], [%1], %2, [%3];"
        :: "r"(dst), "l"(src), "r"(bytes), "r"(mb) : "memory");
}

// wide rows (128B): chunk xor key r&7
__device__ __forceinline__ uint32_t inrowA(int r, int b) {
    return (uint32_t)(((((b >> 4) ^ (r & 7)) << 4)) | (b & 15));
}
__device__ __forceinline__ size_t off_hi(int row, int k) {
    return (size_t)(k >> 5) * ACH + (size_t)row * 128 + inrowA(row, (k & 31) * 2);
}
__device__ __forceinline__ size_t off_lo(int row, int k) {
    return (size_t)(k >> 5) * ACH + (size_t)row * 128 + inrowA(row, 64 + (k & 31) * 2);
}
// narrow rows (64B): chunk xor key (r>>1)&3
__device__ __forceinline__ uint32_t inrowB(int r, int b) {
    return (uint32_t)(((((b >> 4) ^ ((r >> 1) & 3)) << 4)) | (b & 15));
}
__device__ __forceinline__ size_t off_b(int row, int k) {       // B-family (256-row chunks)
    return (size_t)(k >> 5) * BCH + (size_t)row * 64 + inrowB(row, (k & 31) * 2);
}
__device__ __forceinline__ size_t off_n(int row, int k) {       // narrow (131072-row chunks)
    return (size_t)(k >> 5) * HCH + (size_t)row * 64 + inrowB(row, (k & 31) * 2);
}
__device__ __forceinline__ void store_splitH(char* base, int row, int k, float x, float y) {
    uint32_t H, L; split2(x, y, H, L);
    *(uint32_t*)(base + off_hi(row, k)) = H;
    *(uint32_t*)(base + off_lo(row, k)) = L;
}

// ---------------- wide GEMM (out): A split hi/lo, 2-pass ----------------

__device__ __forceinline__ void issue_chunk(uint32_t sb, int st,
    const char* Aimg, const char* Bimg, int c)
{
    const uint32_t buf = sb + (uint32_t)st * STAGE;
    const uint32_t mb  = sb + OFF_MB + (uint32_t)st * 8;
    MBAR_EXPECT(mb, 24576u);
    bulk_cp(buf + OFF_A, Aimg + (size_t)c * ACH, 16384, mb);
    bulk_cp(buf + OFF_B, Bimg + (size_t)c * BCH, 8192, mb);
}

__device__ __forceinline__ void gemm_compute(uint32_t sb,
    const char* __restrict__ Aimg, const char* __restrict__ Bimg,
    float acc[2][8][4])
{
    const int tid = threadIdx.x;
    const int lane = tid & 31, wid = tid >> 5;
    const int wm = wid >> 1, wn = wid & 1;

#pragma unroll
    for (int mt = 0; mt < 2; ++mt)
#pragma unroll
        for (int nt = 0; nt < 8; ++nt)
#pragma unroll
            for (int i = 0; i < 4; ++i) acc[mt][nt][i] = 0.f;

    if (tid == 0) {
#pragma unroll
        for (int s = 0; s < NSTAGE; ++s) {
            MBAR_INIT(sb + OFF_MB + s * 8, 1);
            MBAR_INIT(sb + OFF_MB + 24 + s * 8, 8);
        }
    }
    __syncthreads();
    if (tid == 0) {
        issue_chunk(sb, 0, Aimg, Bimg, 0);
        issue_chunk(sb, 1, Aimg, Bimg, 1);
    }

    const uint32_t xr     = lane & 7;
    const uint32_t a_base = (uint32_t)(wm*32 + (lane & 15)) * 128;
    const uint32_t a_kh   = lane >> 4;
    const uint32_t b_row  = (lane & 7) + ((lane & 16) >> 1);
    const uint32_t b_base = ((uint32_t)(wn*64) + b_row) * 64;
    const uint32_t b_kh   = (lane >> 3) & 1;
    const uint32_t bxr    = (lane & 6) >> 1;

#pragma unroll
    for (int c = 0; c < 8; ++c) {
        const int st = c % NSTAGE;
        if (tid == 0 && c + 2 < 8) {
            const int cn = c + 2, st2 = cn % NSTAGE;
            if (cn >= NSTAGE) { MBAR_WAIT(sb + OFF_MB + 24 + st2 * 8, ((cn - NSTAGE) / NSTAGE) & 1); }
            issue_chunk(sb, st2, Aimg, Bimg, cn);
        }
        MBAR_WAIT(sb + OFF_MB + st * 8, (c / NSTAGE) & 1);
        const uint32_t buf = sb + (uint32_t)st * STAGE;
#pragma unroll
        for (int s = 0; s < 2; ++s) {
            const uint32_t ach = (uint32_t)s*2 + a_kh;
            const uint32_t ax_h = ((ach ^ xr) << 4), ax_l = (((ach + 4) ^ xr) << 4);
            const uint32_t bx   = (((uint32_t)s*2 + b_kh) ^ bxr) << 4;
            uint32_t ah[2][4], al[2][4];
#pragma unroll
            for (int mt = 0; mt < 2; ++mt) {
                const uint32_t ao = buf + OFF_A + a_base + (uint32_t)mt*2048;
                ldsm_x4(ah[mt], ao + ax_h);
                ldsm_x4(al[mt], ao + ax_l);
            }
#pragma unroll
            for (int half = 0; half < 2; ++half) {
                uint32_t bh[2][4];
#pragma unroll
                for (int p = 0; p < 2; ++p) {
                    const uint32_t bo = buf + OFF_B + b_base + (uint32_t)(half*2 + p)*1024;
                    ldsm_x4(bh[p], bo + bx);
                }
#pragma unroll
                for (int mt = 0; mt < 2; ++mt)
#pragma unroll
                    for (int p = 0; p < 2; ++p)
#pragma unroll
                        for (int q = 0; q < 2; ++q)
                            mma16816(acc[mt][half*4 + p*2 + q], ah[mt], &bh[p][q*2]);
#pragma unroll
                for (int mt = 0; mt < 2; ++mt)
#pragma unroll
                    for (int p = 0; p < 2; ++p)
#pragma unroll
                        for (int q = 0; q < 2; ++q)
                            mma16816(acc[mt][half*4 + p*2 + q], al[mt], &bh[p][q*2]);
            }
        }
        if (lane == 0) MBAR_ARRIVE(sb + OFF_MB + 24 + st * 8);
    }
}

// ---------------- narrow GEMM (proj/tri): A hi-only, single pass ----------------

__device__ __forceinline__ void issue_chunk1(uint32_t sb, int st,
    const char* Aimg, const char* Bimg, int c)
{
    const uint32_t buf = sb + (uint32_t)st * STAGE1;
    const uint32_t mb  = sb + OFF_MB + (uint32_t)st * 8;
    MBAR_EXPECT(mb, 16384u);
    bulk_cp(buf,          Aimg + (size_t)c * HCH, 8192, mb);
    bulk_cp(buf + OFF_B1, Bimg + (size_t)c * BCH, 8192, mb);
}

__device__ __forceinline__ void gemm_compute1(uint32_t sb,
    const char* __restrict__ Aimg, const char* __restrict__ Bimg,
    float acc[2][8][4])
{
    const int tid = threadIdx.x;
    const int lane = tid & 31, wid = tid >> 5;
    const int wm = wid >> 1, wn = wid & 1;

#pragma unroll
    for (int mt = 0; mt < 2; ++mt)
#pragma unroll
        for (int nt = 0; nt < 8; ++nt)
#pragma unroll
            for (int i = 0; i < 4; ++i) acc[mt][nt][i] = 0.f;

    if (tid == 0) {
#pragma unroll
        for (int s = 0; s < NSTAGE; ++s) {
            MBAR_INIT(sb + OFF_MB + s * 8, 1);
            MBAR_INIT(sb + OFF_MB + 24 + s * 8, 8);
        }
    }
    __syncthreads();
    if (tid == 0) {
        issue_chunk1(sb, 0, Aimg, Bimg, 0);
        issue_chunk1(sb, 1, Aimg, Bimg, 1);
    }

    const uint32_t a_base = (uint32_t)(wm*32 + (lane & 15)) * 64;
    const uint32_t a_kh   = lane >> 4;
    const uint32_t axr    = (lane >> 1) & 3;
    const uint32_t b_row  = (lane & 7) + ((lane & 16) >> 1);
    const uint32_t b_base = ((uint32_t)(wn*64) + b_row) * 64;
    const uint32_t b_kh   = (lane >> 3) & 1;
    const uint32_t bxr    = (lane & 6) >> 1;

#pragma unroll
    for (int c = 0; c < 8; ++c) {
        const int st = c % NSTAGE;
        if (tid == 0 && c + 2 < 8) {
            const int cn = c + 2, st2 = cn % NSTAGE;
            if (cn >= NSTAGE) { MBAR_WAIT(sb + OFF_MB + 24 + st2 * 8, ((cn - NSTAGE) / NSTAGE) & 1); }
            issue_chunk1(sb, st2, Aimg, Bimg, cn);
        }
        MBAR_WAIT(sb + OFF_MB + st * 8, (c / NSTAGE) & 1);
        const uint32_t buf = sb + (uint32_t)st * STAGE1;
#pragma unroll
        for (int s = 0; s < 2; ++s) {
            const uint32_t ax = (((uint32_t)s*2 + a_kh) ^ axr) << 4;
            const uint32_t bx = (((uint32_t)s*2 + b_kh) ^ bxr) << 4;
            uint32_t ah[2][4];
#pragma unroll
            for (int mt = 0; mt < 2; ++mt)
                ldsm_x4(ah[mt], buf + a_base + (uint32_t)mt*1024 + ax);
#pragma unroll
            for (int half = 0; half < 2; ++half) {
                uint32_t bh[2][4];
#pragma unroll
                for (int p = 0; p < 2; ++p) {
                    const uint32_t bo = buf + OFF_B1 + b_base + (uint32_t)(half*2 + p)*1024;
                    ldsm_x4(bh[p], bo + bx);
                }
#pragma unroll
                for (int mt = 0; mt < 2; ++mt)
#pragma unroll
                    for (int p = 0; p < 2; ++p)
#pragma unroll
                        for (int q = 0; q < 2; ++q)
                            mma16816(acc[mt][half*4 + p*2 + q], ah[mt], &bh[p][q*2]);
            }
        }
        if (lane == 0) MBAR_ARRIVE(sb + OFF_MB + 24 + st * 8);
    }
}

// ---------------- prep kernels ----------------

// pair fp32 -> narrow fp16 hi-only image
extern "C" __global__ void psplit_kernel(const float* __restrict__ pair)
{
    const size_t i = ((size_t)blockIdx.x * 256 + threadIdx.x) * 4;
    const int m = (int)(i >> 8), col = (int)(i & 255);
    float4 v = *(const float4*)(pair + i);
    uint32_t h01 = pack_h2(__float2half_rn(v.x), __float2half_rn(v.y));
    uint32_t h23 = pack_h2(__float2half_rn(v.z), __float2half_rn(v.w));
    *(uint2*)((char*)g_P + off_n(m, col)) = make_uint2(h01, h23);
}

extern "C" __global__ void wprep_kernel(const float* __restrict__ Wa,
                                        const float* __restrict__ Wb,
                                        const float* __restrict__ Wg,
                                        const float* __restrict__ Wo)
{
    const float* Ws[4] = {Wa, Wb, Wg, Wo};
    const int d = blockIdx.x, c = threadIdx.x;
    const size_t off = off_b(d, c);
#pragma unroll
    for (int w = 0; w < 4; ++w) {
        __half h = __float2half_rn(Ws[w][c*256 + d]);
        *(__half*)((char*)g_W + (size_t)w * SLB + off) = h;
    }
}

// ---------------- GEMM kernels ----------------

// grid (6, 1024): x = w*2 + nt, y = m-tile. Single-pass narrow GEMM.
extern "C" __global__ void __launch_bounds__(THREADS, 2)
proj_kernel(const float* __restrict__ ba, const float* __restrict__ bb,
            const float* __restrict__ bg)
{
    extern __shared__ char smem[];
    const uint32_t sb = smem_u32(smem);
    const int w = blockIdx.x >> 1, nt = blockIdx.x & 1;
    const int m0 = blockIdx.y * 128;

    float acc[2][8][4];
    gemm_compute1(sb,
                  (const char*)g_P + (size_t)m0*64,
                  (const char*)g_W + (size_t)w*SLB + (size_t)nt*8192,
                  acc);
    __syncthreads();

    const float* bias = (w == 0) ? ba : ((w == 1) ? bb : bg);
    const int wid = threadIdx.x >> 5, lane = threadIdx.x & 31;
    const int wm = wid >> 1, wn = wid & 1;
    const int g = lane >> 2, qc = lane & 3;

    if (w == 1) {
        // stage warp tile [32 m][64 n] fp32 -> transposed hi-only store to g_B
        float* stg = (float*)smem + wid * 2080;  // 32*65
#pragma unroll
        for (int mt = 0; mt < 2; ++mt)
#pragma unroll
            for (int ntl = 0; ntl < 8; ++ntl) {
                const int rm = mt*16 + g, cn = ntl*8 + 2*qc;
                float2 bv = *(const float2*)(bias + nt*128 + wn*64 + cn);
                stg[rm*65 + cn]           = acc[mt][ntl][0] + bv.x;
                stg[rm*65 + cn + 1]       = acc[mt][ntl][1] + bv.y;
                stg[(rm + 8)*65 + cn]     = acc[mt][ntl][2] + bv.x;
                stg[(rm + 8)*65 + cn + 1] = acc[mt][ntl][3] + bv.y;
            }
        __syncwarp();
        const int slice = m0 >> 8;
        const int j0 = (m0 & 255) + wm * 32;
        const int m2 = 2 * (lane & 15);
        const int j = j0 + m2;
        char* base = (char*)g_B + (size_t)slice * SLB;
        for (int r = lane >> 4; r < 64; r += 2) {
            const int l = nt*128 + wn*64 + r;
            uint32_t H = pack_h2(__float2half_rn(stg[m2*65 + r]),
                                 __float2half_rn(stg[(m2 + 1)*65 + r]));
            *(uint32_t*)(base + off_b(l, j)) = H;
        }
    } else {
#pragma unroll
        for (int mt = 0; mt < 2; ++mt) {
            const int R0 = m0 + wm*32 + mt*16 + g;
#pragma unroll
            for (int ntl = 0; ntl < 8; ++ntl) {
                const int col = nt*128 + wn*64 + ntl*8 + 2*qc;
                float2 bv = *(const float2*)(bias + col);
                float v0 = acc[mt][ntl][0] + bv.x, v1 = acc[mt][ntl][1] + bv.y;
                float v2 = acc[mt][ntl][2] + bv.x, v3 = acc[mt][ntl][3] + bv.y;
                if (w == 2) {
                    v0 = 1.f/(1.f + __expf(-v0)); v1 = 1.f/(1.f + __expf(-v1));
                    v2 = 1.f/(1.f + __expf(-v2)); v3 = 1.f/(1.f + __expf(-v3));
                    *(float2*)(g_G + (size_t)R0*256 + col)       = make_float2(v0, v1);
                    *(float2*)(g_G + (size_t)(R0 + 8)*256 + col) = make_float2(v2, v3);
                } else {
                    // a-projection: hi-only narrow store
                    *(uint32_t*)((char*)g_A + off_n(R0, col)) =
                        pack_h2(__float2half_rn(v0), __float2half_rn(v1));
                    *(uint32_t*)((char*)g_A + off_n(R0 + 8, col)) =
                        pack_h2(__float2half_rn(v2), __float2half_rn(v3));
                }
            }
        }
    }
}

// grid (4, 512): x = jt + 2*lt, y = slice. h = g * (a_s @ b_s), single-pass.
extern "C" __global__ void __launch_bounds__(THREADS, 2)
tri_kernel()
{
    extern __shared__ char smem[];
    const uint32_t sb = smem_u32(smem);
    const int jt = blockIdx.x & 1, lt = blockIdx.x >> 1;
    const int slice = blockIdx.y;

    float acc[2][8][4];
    gemm_compute1(sb,
                  (const char*)g_A + (size_t)(slice*256 + jt*128)*64,
                  (const char*)g_B + (size_t)slice*SLB + (size_t)lt*8192,
                  acc);

    const int wid = threadIdx.x >> 5, lane = threadIdx.x & 31;
    const int wm = wid >> 1, wn = wid & 1;
    const int g = lane >> 2, qc = lane & 3;
    const int mbase = slice*256 + jt*128 + wm*32;

#pragma unroll
    for (int mt = 0; mt < 2; ++mt) {
        const int R0 = mbase + mt*16 + g;
#pragma unroll
        for (int ntl = 0; ntl < 8; ++ntl) {
            const int col = lt*128 + wn*64 + ntl*8 + 2*qc;
            float2 g0 = *(const float2*)(g_G + (size_t)R0*256 + col);
            float2 g1 = *(const float2*)(g_G + (size_t)(R0 + 8)*256 + col);
            store_splitH((char*)g_H, R0,     col, acc[mt][ntl][0]*g0.x, acc[mt][ntl][1]*g0.y);
            store_splitH((char*)g_H, R0 + 8, col, acc[mt][ntl][2]*g1.x, acc[mt][ntl][3]*g1.y);
        }
    }
}

// grid (2, 1024): x = nt, y = m-tile. out = H @ Wo^T-rows + bo (2-pass, exact H).
extern "C" __global__ void __launch_bounds__(THREADS, 2)
out_kernel(const float* __restrict__ bo, float* __restrict__ out)
{
    extern __shared__ char smem[];
    const uint32_t sb = smem_u32(smem);
    const int nt = blockIdx.x;
    const int m0 = blockIdx.y * 128;

    float acc[2][8][4];
    gemm_compute(sb,
                 (const char*)g_H + (size_t)m0*128,
                 (const char*)g_W + (size_t)3*SLB + (size_t)nt*8192,
                 acc);

    const int wid = threadIdx.x >> 5, lane = threadIdx.x & 31;
    const int wm = wid >> 1, wn = wid & 1;
    const int g = lane >> 2, qc = lane & 3;

#pragma unroll
    for (int mt = 0; mt < 2; ++mt) {
        const int R0 = m0 + wm*32 + mt*16 + g;
#pragma unroll
        for (int ntl = 0; ntl < 8; ++ntl) {
            const int col = nt*128 + wn*64 + ntl*8 + 2*qc;
            float2 bv = *(const float2*)(bo + col);
            *(float2*)(out + (size_t)R0*256 + col) =
                make_float2(acc[mt][ntl][0] + bv.x, acc[mt][ntl][1] + bv.y);
            *(float2*)(out + (size_t)(R0 + 8)*256 + col) =
                make_float2(acc[mt][ntl][2] + bv.x, acc[mt][ntl][3] + bv.y);
        }
    }
}

extern "C" void kernel_launch(void* const* d_in, const int* in_sizes, int n_in,
                              void* d_out, int out_size)
{
    const float* pair = (const float*)d_in[0];
    const float* Wa   = (const float*)d_in[1];
    const float* ba   = (const float*)d_in[2];
    const float* Wb   = (const float*)d_in[3];
    const float* bb   = (const float*)d_in[4];
    const float* Wg   = (const float*)d_in[5];
    const float* bg   = (const float*)d_in[6];
    const float* Wo   = (const float*)d_in[7];
    const float* bo   = (const float*)d_in[8];
    float* out = (float*)d_out;

    cudaFuncSetAttribute(proj_kernel, cudaFuncAttributeMaxDynamicSharedMemorySize, SMEM_TOTAL);
    cudaFuncSetAttribute(tri_kernel,  cudaFuncAttributeMaxDynamicSharedMemorySize, SMEM_TOTAL);
    cudaFuncSetAttribute(out_kernel,  cudaFuncAttributeMaxDynamicSharedMemorySize, SMEM_TOTAL);

    wprep_kernel <<<256,   256>>>(Wa, Wb, Wg, Wo);
    psplit_kernel<<<32768, 256>>>(pair);
    proj_kernel<<<dim3(6, 1024), THREADS, SMEM_TOTAL>>>(ba, bb, bg);
    tri_kernel <<<dim3(4, 512),  THREADS, SMEM_TOTAL>>>();
    out_kernel <<<dim3(2, 1024), THREADS, SMEM_TOTAL>>>(bo, out);
}